// round 1
// baseline (speedup 1.0000x reference)
#include <cuda_runtime.h>
#include <cuda_bf16.h>

// Problem constants
#define BB 16
#define FF 32
#define CC 32
#define NN 200
#define TT 48
#define SS 3
#define NT 8      // n-tile per agg CTA
#define MT 5      // m-chunk
#define NCHUNK (NN / MT)   // 40

// Scratch buffers (device globals; no allocation allowed)
__device__ float g_wh[SS][BB][NN][TT * CC];     // Wh, layout [s][b][n][t][c]
__device__ float g_f1[SS][BB][NN][TT];
__device__ float g_f2[SS][BB][NN][TT];
__device__ float g_f2max[SS][BB][TT];
__device__ float g_y[6][BB][NN][TT * CC];       // GAT outputs, slot = 2*s + hop

// ---------------------------------------------------------------------------
// Wh + f1/f2 kernel. grid (NN, BB, SS), block 256.
// layout==0: input is x with layout (b,f,n,t). layout==1: input is g_y[2s],
// layout [b][n][t][c].
// ---------------------------------------------------------------------------
__global__ __launch_bounds__(256) void wh_kernel(
    const float* __restrict__ xin,
    const float* __restrict__ Wb,
    const float* __restrict__ ab,
    int layout)
{
    const int n = blockIdx.x, b = blockIdx.y, s = blockIdx.z;
    __shared__ float xs[TT * FF];    // [t][f]
    __shared__ float Ws[FF * CC];    // [f][c]
    __shared__ float as_[2 * CC];
    __shared__ float whs[TT * CC];   // [t][c]
    const int tid = threadIdx.x;

    const float* W = Wb + (s * BB + b) * (FF * CC);
    const float* a = ab + (s * BB + b) * (2 * CC);

    if (layout == 0) {
        for (int idx = tid; idx < TT * FF; idx += 256) {
            int f = idx / TT, t = idx % TT;
            xs[t * FF + f] = xin[((b * FF + f) * NN + n) * TT + t];
        }
    } else {
        const float* src = &g_y[2 * s][b][n][0];   // [t][c] contiguous
        for (int idx = tid; idx < TT * FF; idx += 256) xs[idx] = src[idx];
    }
    for (int idx = tid; idx < FF * CC; idx += 256) Ws[idx] = W[idx];
    if (tid < 2 * CC) as_[tid] = a[tid];
    __syncthreads();

    // Wh[c][t] = sum_f xs[t][f] * Ws[f][c]
    #pragma unroll
    for (int k = 0; k < 6; k++) {
        int idx = tid + 256 * k;          // idx < 1536
        int c = idx & 31, t = idx >> 5;
        float v = 0.f;
        #pragma unroll
        for (int f = 0; f < FF; f += 4) {
            float4 xv = *(const float4*)&xs[t * FF + f];
            v += xv.x * Ws[(f    ) * CC + c];
            v += xv.y * Ws[(f + 1) * CC + c];
            v += xv.z * Ws[(f + 2) * CC + c];
            v += xv.w * Ws[(f + 3) * CC + c];
        }
        whs[idx] = v;
        g_wh[s][b][n][idx] = v;
    }
    __syncthreads();

    if (tid < TT) {
        float v1 = 0.f, v2 = 0.f;
        #pragma unroll 8
        for (int c = 0; c < CC; c++) {
            float wv = whs[tid * CC + c];
            v1 += wv * as_[c];
            v2 += wv * as_[CC + c];
        }
        g_f1[s][b][n][tid] = v1;
        g_f2[s][b][n][tid] = v2;
    }
}

// ---------------------------------------------------------------------------
// f2max over n. grid (BB, SS), block 64.
// ---------------------------------------------------------------------------
__global__ void f2max_kernel()
{
    const int b = blockIdx.x, s = blockIdx.y, t = threadIdx.x;
    if (t < TT) {
        float m = -1e30f;
        for (int n = 0; n < NN; n++) m = fmaxf(m, g_f2[s][b][n][t]);
        g_f2max[s][b][t] = m;
    }
}

// ---------------------------------------------------------------------------
// Attention-aggregation (fused masked softmax + weighted sum).
// grid (NN/NT, BB, SS), block 256. hop: 0 -> ELU epilogue, 1 -> ReLU.
// Thread mapping for accumulation: c = tid&31, g = tid>>5, owns t in [6g,6g+6).
// ---------------------------------------------------------------------------
__global__ __launch_bounds__(256) void agg_kernel(const int* __restrict__ support, int hop)
{
    const int nt = blockIdx.x, b = blockIdx.y, s = blockIdx.z;
    const int n0 = nt * NT;
    const int tid = threadIdx.x;

    __shared__ float whs[MT * TT * CC];     // [m][t][c]  30720 B
    __shared__ float ws_[NT * MT * TT];     // [n][m][t]   7680 B
    __shared__ float f1s[NT * TT];
    __shared__ float mhs[NT * TT];
    __shared__ float zs [NT * TT];
    __shared__ float f2c[MT * TT];
    __shared__ float fms[TT];
    __shared__ float masks[NT * MT];

    if (tid < TT) fms[tid] = g_f2max[s][b][tid];
    for (int idx = tid; idx < NT * TT; idx += 256) {
        int nn = idx / TT, t = idx % TT;
        f1s[idx] = g_f1[s][b][n0 + nn][t];
        zs[idx] = 0.f;
    }
    __syncthreads();
    for (int idx = tid; idx < NT * TT; idx += 256) {
        float sv = f1s[idx] + fms[idx % TT];
        mhs[idx] = fmaxf(sv, 0.2f * sv);       // upper bound on row max of e
    }

    const int c = tid & 31, g = tid >> 5, tb = 6 * g;
    float acc[NT][6];
    #pragma unroll
    for (int i = 0; i < NT; i++)
        #pragma unroll
        for (int j = 0; j < 6; j++) acc[i][j] = 0.f;

    const int* adjrow = support + ((b * SS + s) * NN + n0) * NN;

    for (int chunk = 0; chunk < NCHUNK; chunk++) {
        const int m0 = chunk * MT;
        __syncthreads();   // protect prev step2 reads of whs/ws_

        if (tid < NT * MT) {
            int nn = tid / MT, mm = tid % MT;
            masks[tid] = (adjrow[nn * NN + m0 + mm] > 0) ? 1.f : 0.f;
        }
        if (tid < MT * TT) f2c[tid] = g_f2[s][b][m0 + tid / TT][tid % TT];
        {
            const float4* src = (const float4*)&g_wh[s][b][m0][0];
            float4* dst = (float4*)whs;
            for (int i = tid; i < MT * TT * CC / 4; i += 256) dst[i] = src[i];
        }
        __syncthreads();

        // step 1: weights + partial Z. task idx = (nn, t)
        #pragma unroll
        for (int p = 0; p < 2; p++) {
            int idx = tid + 256 * p;
            if (idx < NT * TT) {
                int nn = idx / TT, t = idx % TT;
                float f1v = f1s[idx], mhv = mhs[idx], z = 0.f;
                #pragma unroll
                for (int m = 0; m < MT; m++) {
                    float sv = f1v + f2c[m * TT + t];
                    float e = fmaxf(sv, 0.2f * sv);
                    float w = masks[nn * MT + m] * __expf(e - mhv);
                    ws_[(nn * MT + m) * TT + t] = w;
                    z += w;
                }
                zs[idx] += z;
            }
        }
        __syncthreads();

        // step 2: accumulate acc[n][j] += w[n][m][t] * Wh[m][t][c]
        #pragma unroll
        for (int m = 0; m < MT; m++) {
            float whv[6];
            #pragma unroll
            for (int j = 0; j < 6; j++) whv[j] = whs[m * (TT * CC) + (tb + j) * CC + c];
            #pragma unroll
            for (int nn = 0; nn < NT; nn++) {
                const float* wp = &ws_[(nn * MT + m) * TT + tb];
                float2 w01 = *(const float2*)(wp);
                float2 w23 = *(const float2*)(wp + 2);
                float2 w45 = *(const float2*)(wp + 4);
                acc[nn][0] += w01.x * whv[0];
                acc[nn][1] += w01.y * whv[1];
                acc[nn][2] += w23.x * whv[2];
                acc[nn][3] += w23.y * whv[3];
                acc[nn][4] += w45.x * whv[4];
                acc[nn][5] += w45.y * whv[5];
            }
        }
    }

    // finalize: normalize + activation. zs complete (written before last sync).
    const int slot = 2 * s + hop;
    #pragma unroll
    for (int nn = 0; nn < NT; nn++) {
        #pragma unroll
        for (int j = 0; j < 6; j++) {
            int t = tb + j;
            float z = fmaxf(zs[nn * TT + t], 1e-30f);
            float h = __fdividef(acc[nn][j], z);
            float y;
            if (hop == 0) y = (h > 0.f) ? h : (__expf(h) - 1.f);   // ELU
            else          y = fmaxf(h, 0.f);                        // relu(elu()) == relu()
            g_y[slot][b][n0 + nn][t * CC + c] = y;
        }
    }
}

// ---------------------------------------------------------------------------
// Final concat + 1x1 conv. grid (NN, BB), block 192.
// thread: og = tid%16 (o = og + 16i, i<4), tg = tid/16 (t = 4tg + j, j<4).
// ---------------------------------------------------------------------------
__global__ __launch_bounds__(192) void mlp_kernel(
    const float* __restrict__ x,
    const float* __restrict__ mw,
    const float* __restrict__ mb,
    float* __restrict__ out)
{
    const int n = blockIdx.x, b = blockIdx.y;
    const int tid = threadIdx.x;
    __shared__ float hb[TT * 32];     // [t][c] chunk
    __shared__ float wb[64 * 36];     // [o][c] chunk, padded row 36

    const int og = tid % 16, tg = tid / 16;   // tg in [0,12)
    float acc[4][4];
    #pragma unroll
    for (int i = 0; i < 4; i++)
        #pragma unroll
        for (int j = 0; j < 4; j++) acc[i][j] = 0.f;

    for (int blk = 0; blk < 7; blk++) {
        __syncthreads();
        if (blk == 0) {
            for (int idx = tid; idx < TT * 32; idx += 192) {
                int f = idx / TT, t = idx % TT;
                hb[t * 32 + f] = x[((b * FF + f) * NN + n) * TT + t];
            }
        } else {
            const float* src = &g_y[blk - 1][b][n][0];
            for (int idx = tid; idx < TT * 32; idx += 192) hb[idx] = src[idx];
        }
        for (int idx = tid; idx < 64 * 32; idx += 192) {
            int o = idx / 32, c = idx % 32;
            wb[o * 36 + c] = mw[o * 224 + blk * 32 + c];
        }
        __syncthreads();

        #pragma unroll
        for (int cc = 0; cc < 32; cc += 4) {
            float4 hv[4], wv[4];
            #pragma unroll
            for (int j = 0; j < 4; j++) hv[j] = *(const float4*)&hb[(tg * 4 + j) * 32 + cc];
            #pragma unroll
            for (int i = 0; i < 4; i++) wv[i] = *(const float4*)&wb[(og + 16 * i) * 36 + cc];
            #pragma unroll
            for (int i = 0; i < 4; i++)
                #pragma unroll
                for (int j = 0; j < 4; j++) {
                    acc[i][j] += wv[i].x * hv[j].x + wv[i].y * hv[j].y
                               + wv[i].z * hv[j].z + wv[i].w * hv[j].w;
                }
        }
    }

    #pragma unroll
    for (int i = 0; i < 4; i++) {
        int o = og + 16 * i;
        float bias = mb[o];
        float4 r = make_float4(acc[i][0] + bias, acc[i][1] + bias,
                               acc[i][2] + bias, acc[i][3] + bias);
        *(float4*)&out[((b * 64 + o) * NN + n) * TT + tg * 4] = r;
    }
}

// ---------------------------------------------------------------------------
extern "C" void kernel_launch(void* const* d_in, const int* in_sizes, int n_in,
                              void* d_out, int out_size)
{
    const float* x       = (const float*)d_in[0];
    const int*   support = (const int*)  d_in[1];
    const float* W1      = (const float*)d_in[2];
    const float* a1      = (const float*)d_in[3];
    const float* WK      = (const float*)d_in[4];
    const float* aK      = (const float*)d_in[5];
    const float* mw      = (const float*)d_in[6];
    const float* mb      = (const float*)d_in[7];
    float* out = (float*)d_out;

    dim3 gwh(NN, BB, SS);
    dim3 gfm(BB, SS);
    dim3 gagg(NN / NT, BB, SS);
    dim3 gmlp(NN, BB);

    // hop 1 (from x, W1/a1) -> g_y[2s] with ELU
    wh_kernel<<<gwh, 256>>>(x, W1, a1, 0);
    f2max_kernel<<<gfm, 64>>>();
    agg_kernel<<<gagg, 256>>>(support, 0);

    // hop 2 (from g_y[2s], WK/aK) -> g_y[2s+1] with ReLU
    wh_kernel<<<gwh, 256>>>(x, WK, aK, 1);
    f2max_kernel<<<gfm, 64>>>();
    agg_kernel<<<gagg, 256>>>(support, 1);

    // concat + 1x1 conv
    mlp_kernel<<<gmlp, 192>>>(x, mw, mb, out);
}

// round 2
// speedup vs baseline: 1.0578x; 1.0578x over previous
#include <cuda_runtime.h>
#include <cuda_bf16.h>

// Problem constants
#define BB 16
#define FF 32
#define CC 32
#define NN 200
#define TT 48
#define SS 3
#define NT 8          // n-tile per agg CTA
#define MT 5          // m-chunk
#define NCHUNK (NN / MT)
#define NTFLAT (NN * TT)   // 9600 flat (n,t) rows

// Scratch (device globals)
__device__ float g_wh[SS][BB][NTFLAT * CC];   // [(n,t)][c] row-major
__device__ float g_f1[SS][BB][NTFLAT];
__device__ float g_f2[SS][BB][NTFLAT];
__device__ float g_f2max[SS][BB][TT];
__device__ float g_y[6][BB][NTFLAT * CC];     // slot = 2*s + hop, [(n,t)][c]

// ---------------------------------------------------------------------------
// Wh + f1/f2. GEMM M=9600 (flat n,t) x K=32 x N=32 per (s,b).
// grid (75, BB, SS), block 256. CTA: 128 rows. Thread: 8 rows x 2 channels.
// layout==0: input x (b,f,(n,t)) K-major.  layout==1: g_y[2s] (row-major).
// ---------------------------------------------------------------------------
__global__ __launch_bounds__(256) void wh_kernel(
    const float* __restrict__ xin,
    const float* __restrict__ Wb,
    const float* __restrict__ ab,
    int layout)
{
    const int b = blockIdx.y, s = blockIdx.z;
    const int base = blockIdx.x * 128;
    const int tid = threadIdx.x;

    __shared__ float xs[128 * 33];   // [row][f], pad 33
    __shared__ float Ws[FF * CC];    // [f][c]
    __shared__ float as_[2 * CC];

    if (layout == 0) {
        // x[b][f][base..base+128): 32 rows of 128 contiguous floats
        const float* src = xin + (size_t)b * FF * NTFLAT + base;
        #pragma unroll
        for (int k = 0; k < 4; k++) {
            int idx4 = tid + 256 * k;            // < 1024
            int f = idx4 >> 5, r4 = (idx4 & 31) * 4;
            float4 v = *(const float4*)(src + (size_t)f * NTFLAT + r4);
            xs[(r4 + 0) * 33 + f] = v.x;
            xs[(r4 + 1) * 33 + f] = v.y;
            xs[(r4 + 2) * 33 + f] = v.z;
            xs[(r4 + 3) * 33 + f] = v.w;
        }
    } else {
        const float* src = &g_y[2 * s][b][(size_t)base * CC];
        #pragma unroll
        for (int k = 0; k < 4; k++) {
            int idx4 = tid + 256 * k;
            int row = idx4 >> 3, q = (idx4 & 7) * 4;
            float4 v = *(const float4*)(src + idx4 * 4);
            xs[row * 33 + q + 0] = v.x;
            xs[row * 33 + q + 1] = v.y;
            xs[row * 33 + q + 2] = v.z;
            xs[row * 33 + q + 3] = v.w;
        }
    }
    {
        const float* W = Wb + (s * BB + b) * (FF * CC);
        const float4* Wv = (const float4*)W;
        if (tid < 256) { ((float4*)Ws)[tid] = Wv[tid]; }
        if (tid < 2 * CC) as_[tid] = ab[(s * BB + b) * (2 * CC) + tid];
    }
    __syncthreads();

    const int cg = tid & 15, rg = tid >> 4;   // c pair 2*cg, rows rg*8..+7
    const int r0 = rg * 8;
    float acc[8][2];
    #pragma unroll
    for (int i = 0; i < 8; i++) { acc[i][0] = 0.f; acc[i][1] = 0.f; }

    #pragma unroll 8
    for (int f = 0; f < FF; f++) {
        float2 wv = *(const float2*)&Ws[f * CC + 2 * cg];
        #pragma unroll
        for (int i = 0; i < 8; i++) {
            float xv = xs[(r0 + i) * 33 + f];
            acc[i][0] += xv * wv.x;
            acc[i][1] += xv * wv.y;
        }
    }

    // store Wh
    float* whp = &g_wh[s][b][0];
    #pragma unroll
    for (int i = 0; i < 8; i++) {
        *(float2*)&whp[(size_t)(base + r0 + i) * CC + 2 * cg] =
            make_float2(acc[i][0], acc[i][1]);
    }

    // f1/f2 via 16-lane shuffle reduction
    float a1l = as_[2 * cg], a1h = as_[2 * cg + 1];
    float a2l = as_[CC + 2 * cg], a2h = as_[CC + 2 * cg + 1];
    #pragma unroll
    for (int i = 0; i < 8; i++) {
        float p1 = acc[i][0] * a1l + acc[i][1] * a1h;
        float p2 = acc[i][0] * a2l + acc[i][1] * a2h;
        #pragma unroll
        for (int off = 8; off >= 1; off >>= 1) {
            p1 += __shfl_xor_sync(0xffffffffu, p1, off);
            p2 += __shfl_xor_sync(0xffffffffu, p2, off);
        }
        if (cg == 0) {
            g_f1[s][b][base + r0 + i] = p1;
            g_f2[s][b][base + r0 + i] = p2;
        }
    }
}

// ---------------------------------------------------------------------------
// f2max over n. grid (BB, SS), block 64.
// ---------------------------------------------------------------------------
__global__ void f2max_kernel()
{
    const int b = blockIdx.x, s = blockIdx.y, t = threadIdx.x;
    if (t < TT) {
        float m = -1e30f;
        for (int n = 0; n < NN; n++) m = fmaxf(m, g_f2[s][b][n * TT + t]);
        g_f2max[s][b][t] = m;
    }
}

// ---------------------------------------------------------------------------
// Attention-aggregation. grid (NN/NT, BB, SS), block 256.
// Thread tile: cg = tid&15 (2 channels), tg = tid>>4 (3 t's), all 8 nn.
// ---------------------------------------------------------------------------
__global__ __launch_bounds__(256) void agg_kernel(const int* __restrict__ support, int hop)
{
    const int nt = blockIdx.x, b = blockIdx.y, s = blockIdx.z;
    const int n0 = nt * NT;
    const int tid = threadIdx.x;

    __shared__ float whs[MT * TT * CC];   // [m][t][c]   30720 B
    __shared__ float ws_[MT * TT * NT];   // [m][t][nn]   7680 B
    __shared__ float f1s[TT * NT];        // [t][nn]
    __shared__ float mhs[TT * NT];
    __shared__ float zs [TT * NT];
    __shared__ float f2c[MT * TT];        // [m][t]
    __shared__ float fms[TT];
    __shared__ float masks[NT * MT];      // [nn][m]

    if (tid < TT) fms[tid] = g_f2max[s][b][tid];
    __syncthreads();
    for (int idx = tid; idx < TT * NT; idx += 256) {
        int t = idx >> 3, nn = idx & 7;
        float f1v = g_f1[s][b][(n0 + nn) * TT + t];
        f1s[idx] = f1v;
        zs[idx] = 0.f;
        float sv = f1v + fms[t];
        mhs[idx] = fmaxf(sv, 0.2f * sv);
    }

    const int cg = tid & 15, tg = tid >> 4;   // c = 2*cg(+1), t = 3*tg+j
    float acc[NT][6];
    #pragma unroll
    for (int i = 0; i < NT; i++)
        #pragma unroll
        for (int j = 0; j < 6; j++) acc[i][j] = 0.f;

    const int* adjrow = support + (((size_t)b * SS + s) * NN + n0) * NN;
    const float* whsrc_base = &g_wh[s][b][0];
    const float* f2src = &g_f2[s][b][0];

    for (int chunk = 0; chunk < NCHUNK; chunk++) {
        const int m0 = chunk * MT;
        __syncthreads();   // prior step2 done with whs/ws_

        if (tid < NT * MT) {
            int nn = tid / MT, mm = tid % MT;
            masks[tid] = (adjrow[nn * NN + m0 + mm] > 0) ? 1.f : 0.f;
        }
        if (tid < MT * TT) {
            int m = tid / TT, t = tid % TT;
            f2c[tid] = f2src[(m0 + m) * TT + t];
        }
        {
            const float4* src = (const float4*)(whsrc_base + (size_t)m0 * TT * CC);
            float4* dst = (float4*)whs;
            for (int i = tid; i < MT * TT * CC / 4; i += 256) dst[i] = src[i];
        }
        __syncthreads();

        // step 1: weights + partial Z. 384 tasks, idx = t*8+nn
        #pragma unroll
        for (int p = 0; p < 2; p++) {
            int idx = tid + 256 * p;
            if (idx < TT * NT) {
                int t = idx >> 3, nn = idx & 7;
                float f1v = f1s[idx], mhv = mhs[idx], z = 0.f;
                #pragma unroll
                for (int m = 0; m < MT; m++) {
                    float sv = f1v + f2c[m * TT + t];
                    float e = fmaxf(sv, 0.2f * sv);
                    float w = masks[nn * MT + m] * __expf(e - mhv);
                    ws_[(m * TT + t) * NT + nn] = w;
                    z += w;
                }
                zs[idx] += z;
            }
        }
        __syncthreads();

        // step 2: acc[nn][j*2+q] += ws_[m][t][nn] * whs[m][t][2cg+q]
        #pragma unroll
        for (int m = 0; m < MT; m++) {
            float2 whv[3];
            float4 wa[3], wb[3];
            #pragma unroll
            for (int j = 0; j < 3; j++) {
                int t = 3 * tg + j;
                whv[j] = *(const float2*)&whs[(m * TT + t) * CC + 2 * cg];
                const float4* wp = (const float4*)&ws_[(m * TT + t) * NT];
                wa[j] = wp[0];
                wb[j] = wp[1];
            }
            #pragma unroll
            for (int j = 0; j < 3; j++) {
                acc[0][2*j]   += wa[j].x * whv[j].x;  acc[0][2*j+1] += wa[j].x * whv[j].y;
                acc[1][2*j]   += wa[j].y * whv[j].x;  acc[1][2*j+1] += wa[j].y * whv[j].y;
                acc[2][2*j]   += wa[j].z * whv[j].x;  acc[2][2*j+1] += wa[j].z * whv[j].y;
                acc[3][2*j]   += wa[j].w * whv[j].x;  acc[3][2*j+1] += wa[j].w * whv[j].y;
                acc[4][2*j]   += wb[j].x * whv[j].x;  acc[4][2*j+1] += wb[j].x * whv[j].y;
                acc[5][2*j]   += wb[j].y * whv[j].x;  acc[5][2*j+1] += wb[j].y * whv[j].y;
                acc[6][2*j]   += wb[j].z * whv[j].x;  acc[6][2*j+1] += wb[j].z * whv[j].y;
                acc[7][2*j]   += wb[j].w * whv[j].x;  acc[7][2*j+1] += wb[j].w * whv[j].y;
            }
        }
    }

    // finalize
    const int slot = 2 * s + hop;
    float* yp = &g_y[slot][b][0];
    #pragma unroll
    for (int nn = 0; nn < NT; nn++) {
        #pragma unroll
        for (int j = 0; j < 3; j++) {
            int t = 3 * tg + j;
            float z = fmaxf(zs[t * NT + nn], 1e-30f);
            float h0 = __fdividef(acc[nn][2*j],   z);
            float h1 = __fdividef(acc[nn][2*j+1], z);
            float y0, y1;
            if (hop == 0) {
                y0 = (h0 > 0.f) ? h0 : (__expf(h0) - 1.f);
                y1 = (h1 > 0.f) ? h1 : (__expf(h1) - 1.f);
            } else {
                y0 = fmaxf(h0, 0.f);
                y1 = fmaxf(h1, 0.f);
            }
            *(float2*)&yp[(size_t)((n0 + nn) * TT + t) * CC + 2 * cg] = make_float2(y0, y1);
        }
    }
}

// ---------------------------------------------------------------------------
// Final concat + 1x1 conv. grid (NN, BB), block 192.
// ---------------------------------------------------------------------------
__global__ __launch_bounds__(192) void mlp_kernel(
    const float* __restrict__ x,
    const float* __restrict__ mw,
    const float* __restrict__ mb,
    float* __restrict__ out)
{
    const int n = blockIdx.x, b = blockIdx.y;
    const int tid = threadIdx.x;
    __shared__ float hb[TT * 32];     // [t][c] chunk
    __shared__ float wb[64 * 36];     // [o][c] chunk, pad 36

    const int og = tid % 16, tg = tid / 16;
    float acc[4][4];
    #pragma unroll
    for (int i = 0; i < 4; i++)
        #pragma unroll
        for (int j = 0; j < 4; j++) acc[i][j] = 0.f;

    for (int blk = 0; blk < 7; blk++) {
        __syncthreads();
        if (blk == 0) {
            for (int idx = tid; idx < TT * 32; idx += 192) {
                int f = idx / TT, t = idx % TT;
                hb[t * 32 + f] = x[((size_t)(b * FF + f) * NN + n) * TT + t];
            }
        } else {
            const float* src = &g_y[blk - 1][b][(size_t)n * TT * CC];
            for (int idx = tid; idx < TT * 32; idx += 192) hb[idx] = src[idx];
        }
        for (int idx = tid; idx < 64 * 32; idx += 192) {
            int o = idx / 32, c = idx % 32;
            wb[o * 36 + c] = mw[o * 224 + blk * 32 + c];
        }
        __syncthreads();

        #pragma unroll
        for (int cc = 0; cc < 32; cc += 4) {
            float4 hv[4], wv[4];
            #pragma unroll
            for (int j = 0; j < 4; j++) hv[j] = *(const float4*)&hb[(tg * 4 + j) * 32 + cc];
            #pragma unroll
            for (int i = 0; i < 4; i++) wv[i] = *(const float4*)&wb[(og + 16 * i) * 36 + cc];
            #pragma unroll
            for (int i = 0; i < 4; i++)
                #pragma unroll
                for (int j = 0; j < 4; j++)
                    acc[i][j] += wv[i].x * hv[j].x + wv[i].y * hv[j].y
                               + wv[i].z * hv[j].z + wv[i].w * hv[j].w;
        }
    }

    #pragma unroll
    for (int i = 0; i < 4; i++) {
        int o = og + 16 * i;
        float bias = mb[o];
        float4 r = make_float4(acc[i][0] + bias, acc[i][1] + bias,
                               acc[i][2] + bias, acc[i][3] + bias);
        *(float4*)&out[((size_t)(b * 64 + o) * NN + n) * TT + tg * 4] = r;
    }
}

// ---------------------------------------------------------------------------
extern "C" void kernel_launch(void* const* d_in, const int* in_sizes, int n_in,
                              void* d_out, int out_size)
{
    const float* x       = (const float*)d_in[0];
    const int*   support = (const int*)  d_in[1];
    const float* W1      = (const float*)d_in[2];
    const float* a1      = (const float*)d_in[3];
    const float* WK      = (const float*)d_in[4];
    const float* aK      = (const float*)d_in[5];
    const float* mw      = (const float*)d_in[6];
    const float* mb      = (const float*)d_in[7];
    float* out = (float*)d_out;

    dim3 gwh(NTFLAT / 128, BB, SS);
    dim3 gfm(BB, SS);
    dim3 gagg(NN / NT, BB, SS);
    dim3 gmlp(NN, BB);

    // hop 1
    wh_kernel<<<gwh, 256>>>(x, W1, a1, 0);
    f2max_kernel<<<gfm, 64>>>();
    agg_kernel<<<gagg, 256>>>(support, 0);

    // hop 2
    wh_kernel<<<gwh, 256>>>(x, WK, aK, 1);
    f2max_kernel<<<gfm, 64>>>();
    agg_kernel<<<gagg, 256>>>(support, 1);

    // concat + 1x1 conv
    mlp_kernel<<<gmlp, 192>>>(x, mw, mb, out);
}